// round 8
// baseline (speedup 1.0000x reference)
#include <cuda_runtime.h>
#include <math.h>

#define NSd   12
#define NCd   4
#define Td    32
#define NZd   512          // T * 16
#define NEQ   384
#define NIN   128
#define DAMPv 1e-4f
#define LS    17           // padded row stride
#define NTHR  128

struct Smem {
    float M[192];             // [A|B] row-major, 12x16
    float MtM[256];
    float x0[12];
    float z[NZd], Qd[NZd], cd[NZd], g[NZd], Pw[NZd];
    float lamE[NEQ], lamU[NIN], lamL[NIN], lo[NIN], up[NIN];
    float Yv[NEQ];
    float Pa[16 * LS], Pb[16 * LS];
    float inv[32 * 16 * LS];  // t<=16: Pinv (fwd);  t>=17: Qbinv (bwd)
    float Uf[17 * 16 * LS];   // Uf[t] = rho*M*Pinv_{t-1}, rows>=12 zero
    float Ub[31 * 16 * LS];   // Ub[t] = rho*M^T*S*Qbinv_{t+1}, full
    int   act[NIN];
    int   fmin, fmax;
};

__device__ __forceinline__ float buildD(const Smem* S, int t, int i, int j, float rho) {
    float v = (t < Td - 1) ? rho * S->MtM[i * 16 + j] : 0.f;
    if (i == j) {
        v += S->Qd[t * 16 + i] + DAMPv;
        if (i < 12) v += rho;
        else {
            int a = S->act[t * 4 + (i - 12)];
            if (a & 1) v += rho;
            if (a & 2) v += rho;
        }
    }
    return v;
}

// split-lane branch-free Gauss-Jordan (single matrix)
__device__ __forceinline__ void gj16s(const float* Psrc, float* dst, int lane) {
    const int r  = lane & 15;
    const int h  = (lane >> 4) & 1;
    const int c0 = h << 3;
    float a[8];
    #pragma unroll
    for (int j = 0; j < 8; ++j) a[j] = Psrc[r * LS + c0 + j];
    #pragma unroll
    for (int k = 0; k < 16; ++k) {
        const int kh = k >> 3, kc = k & 7;
        float p   = __shfl_sync(0xffffffffu, a[kc], k + (kh << 4));
        float inv = __fdividef(1.0f, p);
        float f   = __shfl_sync(0xffffffffu, a[kc], r + (kh << 4));
        float fi  = f * inv;
        bool  isk = (r == k);
        #pragma unroll
        for (int j = 0; j < 8; ++j) {
            float rkj = __shfl_sync(0xffffffffu, a[j], k + (h << 4));
            a[j] = isk ? rkj * inv : a[j] - fi * rkj;
        }
        if (h == kh) a[kc] = isk ? inv : -fi;
    }
    #pragma unroll
    for (int j = 0; j < 8; ++j) dst[r * LS + c0 + j] = a[j];
}

// dual-matrix fused GJ: two independent inversions in one interleaved stream
__device__ __forceinline__ void gj16d(const float* PA, const float* PB,
                                      float* dA, float* dB, int lane) {
    const int r  = lane & 15;
    const int h  = (lane >> 4) & 1;
    const int c0 = h << 3;
    float a[8], bm[8];
    #pragma unroll
    for (int j = 0; j < 8; ++j) {
        a[j]  = PA[r * LS + c0 + j];
        bm[j] = PB[r * LS + c0 + j];
    }
    #pragma unroll
    for (int k = 0; k < 16; ++k) {
        const int kh = k >> 3, kc = k & 7;
        float pa  = __shfl_sync(0xffffffffu, a[kc],  k + (kh << 4));
        float pb  = __shfl_sync(0xffffffffu, bm[kc], k + (kh << 4));
        float fa  = __shfl_sync(0xffffffffu, a[kc],  r + (kh << 4));
        float fb  = __shfl_sync(0xffffffffu, bm[kc], r + (kh << 4));
        float ia  = __fdividef(1.0f, pa);
        float ib  = __fdividef(1.0f, pb);
        float fia = fa * ia;
        float fib = fb * ib;
        bool  isk = (r == k);
        #pragma unroll
        for (int j = 0; j < 8; ++j) {
            float ra = __shfl_sync(0xffffffffu, a[j],  k + (h << 4));
            float rb = __shfl_sync(0xffffffffu, bm[j], k + (h << 4));
            a[j]  = isk ? ra * ia : a[j]  - fia * ra;
            bm[j] = isk ? rb * ib : bm[j] - fib * rb;
        }
        if (h == kh) {
            a[kc]  = isk ? ia : -fia;
            bm[kc] = isk ? ib : -fib;
        }
    }
    #pragma unroll
    for (int j = 0; j < 8; ++j) {
        dA[r * LS + c0 + j] = a[j];
        dB[r * LS + c0 + j] = bm[j];
    }
}

__global__ __launch_bounds__(NTHR, 1)
void mpc_kernel(const float* __restrict__ x0g, const float* __restrict__ Qg,
                const float* __restrict__ cg,  const float* __restrict__ Ag,
                const float* __restrict__ Bg,  const float* __restrict__ log_,
                const float* __restrict__ upg, float* __restrict__ out, int NB)
{
    extern __shared__ float smraw[];
    Smem* S = reinterpret_cast<Smem*>(smraw);
    const int b    = blockIdx.x;
    const int tid  = threadIdx.x;
    const int wid  = tid >> 5;
    const int lane = tid & 31;

    // ---------------- load inputs ----------------
    for (int i = tid; i < NZd; i += NTHR) {
        S->z[i]  = 0.f;
        S->Qd[i] = Qg[b * NZd + i];
        S->cd[i] = cg[b * NZd + i];
    }
    for (int i = tid; i < NEQ; i += NTHR) S->lamE[i] = 0.f;
    for (int i = tid; i < NIN; i += NTHR) {
        S->lamU[i] = 0.f; S->lamL[i] = 0.f;
        S->lo[i]  = log_[b * NIN + i];
        S->up[i]  = upg[b * NIN + i];
        S->act[i] = -1;
    }
    for (int i = tid; i < 192; i += NTHR) {
        int r = i / 16, cc = i % 16;
        S->M[i] = (cc < 12) ? Ag[r * 12 + cc] : Bg[r * 4 + (cc - 12)];
    }
    if (tid < 12) S->x0[tid] = x0g[b * 12 + tid];
    __syncthreads();

    // ---------------- MtM ----------------
    for (int e = tid; e < 256; e += NTHR) {
        int ri = e >> 4, rj = e & 15;
        float a = 0.f;
        #pragma unroll
        for (int k = 0; k < 12; ++k) a += S->M[k * 16 + ri] * S->M[k * 16 + rj];
        S->MtM[e] = a;
    }

    // ---------------- initial rollout (warp 0) ----------------
    if (tid < 32) {
        if (tid < 12) S->z[tid] = S->x0[tid];
        for (int t = 0; t < Td - 1; ++t) {
            __syncwarp();
            if (tid < 12) {
                float acc = 0.f;
                #pragma unroll
                for (int j = 0; j < 12; ++j) acc += S->M[tid * 16 + j] * S->z[t * 16 + j];
                S->z[(t + 1) * 16 + tid] = acc;
            }
        }
    }
    __syncthreads();

    float rho = 1.f;
    for (int al = 0; al < 3; ++al) {
        for (int nt = 0; nt < 3; ++nt) {
            // ---- Yv = rho*r + lamE ----
            if (tid == 0) { S->fmin = 32; S->fmax = -1; }
            for (int idx = tid; idx < NEQ; idx += NTHR) {
                int t = idx / 12, i = idx % 12;
                float r;
                if (t == 0) r = S->z[i] - S->x0[i];
                else {
                    float acc = S->z[t * 16 + i];
                    const float* zp = &S->z[(t - 1) * 16];
                    const float* Mr = &S->M[i * 16];
                    #pragma unroll
                    for (int k = 0; k < 16; ++k) acc -= Mr[k] * zp[k];
                    r = acc;
                }
                S->Yv[idx] = rho * r + S->lamE[idx];
            }
            __syncthreads();
            // ---- gradient + active-set flip tracking ----
            for (int idx = tid; idx < NZd; idx += NTHR) {
                int t = idx >> 4, i = idx & 15;
                float gv = S->Qd[idx] * S->z[idx] + S->cd[idx];
                if (i < 12) gv += S->Yv[t * 12 + i];
                if (t < Td - 1) {
                    const float* Yn = &S->Yv[(t + 1) * 12];
                    float acc = 0.f;
                    #pragma unroll
                    for (int k = 0; k < 12; ++k) acc += S->M[k * 16 + i] * Yn[k];
                    gv -= acc;
                }
                if (i >= 12) {
                    int u = t * 4 + (i - 12);
                    float su = fmaxf(rho * (S->z[idx] - S->up[u]) + S->lamU[u], 0.f);
                    float sl = fmaxf(rho * (S->lo[u] - S->z[idx]) + S->lamL[u], 0.f);
                    gv += su - sl;
                    int a = (su > 0.f ? 1 : 0) | (sl > 0.f ? 2 : 0);
                    if (a != S->act[u]) {
                        S->act[u] = a;
                        atomicMin(&S->fmin, t);
                        atomicMax(&S->fmax, t);
                    }
                }
                S->g[idx] = gv;
            }
            __syncthreads();
            int fmn = (nt == 0) ? 0  : S->fmin;
            int fmx = (nt == 0) ? 31 : S->fmax;
            bool needFactor = (nt == 0) || (fmx >= 0);

            // active set unchanged (nt>0): previous Newton step already minimized this
            // quadratic piece exactly -> g ~ roundoff, dz negligible. Skip solve.
            if (!needFactor) continue;

            {
                int sstart = min(fmn, 31 - fmx);
                if (sstart < 0) sstart = 0;
                if (sstart > 15) sstart = 16;
                for (int s = sstart; s < 16; ++s) {
                    const int tf = s, tb = 31 - s;
                    const bool doF  = (tf >= fmn);
                    const bool doFU = doF && (tf > 0) && (tf - 1 >= fmn);
                    const bool doB  = (s < 15) && (fmx >= tb);
                    const bool doBU = doB && (fmx >= tb + 1);
                    // U builds
                    for (int e = tid; e < 256; e += NTHR) {
                        int ri = e >> 4, rj = e & 15;
                        if (doFU) {
                            float v = 0.f;
                            if (ri < 12) {
                                const float* Pp = &S->inv[(tf - 1) * 16 * LS];
                                const float* Mr = &S->M[ri * 16];
                                float a0 = 0.f, a1 = 0.f;
                                #pragma unroll
                                for (int m = 0; m < 16; m += 2) {
                                    a0 += Mr[m]     * Pp[m * LS + rj];
                                    a1 += Mr[m + 1] * Pp[(m + 1) * LS + rj];
                                }
                                v = rho * (a0 + a1);
                            }
                            S->Uf[tf * 16 * LS + ri * LS + rj] = v;
                        }
                        if (doBU) {
                            const float* Qp = &S->inv[(tb + 1) * 16 * LS];
                            float a0 = 0.f, a1 = 0.f;
                            #pragma unroll
                            for (int m = 0; m < 12; m += 2) {
                                a0 += S->M[m * 16 + ri]       * Qp[m * LS + rj];
                                a1 += S->M[(m + 1) * 16 + ri] * Qp[(m + 1) * LS + rj];
                            }
                            S->Ub[tb * 16 * LS + ri * LS + rj] = rho * (a0 + a1);
                        }
                    }
                    __syncwarp();
                    // P builds
                    for (int e = tid; e < 256; e += NTHR) {
                        int ri = e >> 4, rj = e & 15;
                        if (doF) {
                            float v = buildD(S, tf, ri, rj, rho);
                            if (tf > 0 && ri < 12 && rj < 12) {
                                const float* Ur = &S->Uf[tf * 16 * LS + ri * LS];
                                const float* Mr = &S->M[rj * 16];
                                float a0 = 0.f, a1 = 0.f;
                                #pragma unroll
                                for (int k = 0; k < 16; k += 2) { a0 += Ur[k] * Mr[k]; a1 += Ur[k+1] * Mr[k+1]; }
                                v -= rho * (a0 + a1);
                            }
                            S->Pa[ri * LS + rj] = v;
                        }
                        if (doB) {
                            float v = buildD(S, tb, ri, rj, rho);
                            if (s > 0) {
                                const float* Ur = &S->Ub[tb * 16 * LS + ri * LS];
                                float a0 = 0.f, a1 = 0.f;
                                #pragma unroll
                                for (int k = 0; k < 12; k += 2) {
                                    a0 += Ur[k]     * S->M[k * 16 + rj];
                                    a1 += Ur[k + 1] * S->M[(k + 1) * 16 + rj];
                                }
                                v -= rho * (a0 + a1);
                            }
                            S->Pb[ri * LS + rj] = v;
                        }
                    }
                    __syncthreads();
                    if (wid == 0) {
                        if (doF && doB)
                            gj16d(S->Pa, S->Pb, &S->inv[tf * 16 * LS], &S->inv[tb * 16 * LS], lane);
                        else if (doF)
                            gj16s(S->Pa, &S->inv[tf * 16 * LS], lane);
                        else if (doB)
                            gj16s(S->Pb, &S->inv[tb * 16 * LS], lane);
                    }
                    __syncthreads();
                }
                // ---- middle block t=16 ----
                {
                    const bool doMUf = (fmn <= 15);
                    const bool doMUb = (fmx >= 17);
                    for (int e = tid; e < 256; e += NTHR) {
                        int ri = e >> 4, rj = e & 15;
                        if (doMUf) {
                            float v = 0.f;
                            if (ri < 12) {
                                const float* Pp = &S->inv[15 * 16 * LS];
                                const float* Mr = &S->M[ri * 16];
                                float a0 = 0.f, a1 = 0.f;
                                #pragma unroll
                                for (int m = 0; m < 16; m += 2) {
                                    a0 += Mr[m] * Pp[m * LS + rj];
                                    a1 += Mr[m + 1] * Pp[(m + 1) * LS + rj];
                                }
                                v = rho * (a0 + a1);
                            }
                            S->Uf[16 * 16 * LS + ri * LS + rj] = v;
                        }
                        if (doMUb) {
                            const float* Qp = &S->inv[17 * 16 * LS];
                            float a0 = 0.f, a1 = 0.f;
                            #pragma unroll
                            for (int m = 0; m < 12; m += 2) {
                                a0 += S->M[m * 16 + ri] * Qp[m * LS + rj];
                                a1 += S->M[(m + 1) * 16 + ri] * Qp[(m + 1) * LS + rj];
                            }
                            S->Ub[16 * 16 * LS + ri * LS + rj] = rho * (a0 + a1);
                        }
                    }
                    __syncwarp();
                    for (int e = tid; e < 256; e += NTHR) {
                        int ri = e >> 4, rj = e & 15;
                        float pv = buildD(S, 16, ri, rj, rho);
                        if (ri < 12 && rj < 12) {
                            const float* Ur = &S->Uf[16 * 16 * LS + ri * LS];
                            const float* Mr = &S->M[rj * 16];
                            float a0 = 0.f;
                            #pragma unroll
                            for (int k = 0; k < 16; ++k) a0 += Ur[k] * Mr[k];
                            pv -= rho * a0;
                        }
                        {
                            const float* Ur = &S->Ub[16 * 16 * LS + ri * LS];
                            float a0 = 0.f;
                            #pragma unroll
                            for (int k = 0; k < 12; ++k) a0 += Ur[k] * S->M[k * 16 + rj];
                            pv -= rho * a0;
                        }
                        S->Pa[ri * LS + rj] = pv;
                    }
                    __syncthreads();
                    if (wid == 0) gj16s(S->Pa, &S->inv[16 * 16 * LS], lane);
                    __syncthreads();
                }
            }

            // ---- elimination sweeps (warp 0 fwd, warp 1 bwd, concurrent) ----
            if (wid == 0) {
                float w = (lane < 16) ? S->g[lane] : 0.f;
                for (int t = 1; t <= 15; ++t) {
                    float gv = (lane < 16) ? S->g[t * 16 + lane] : 0.f;
                    const float* Ur = &S->Uf[t * 16 * LS + (lane & 15) * LS];
                    float a0 = 0.f, a1 = 0.f;
                    #pragma unroll
                    for (int k = 0; k < 16; k += 2) {
                        a0 += Ur[k]     * __shfl_sync(0xffffffffu, w, k);
                        a1 += Ur[k + 1] * __shfl_sync(0xffffffffu, w, k + 1);
                    }
                    w = gv + a0 + a1;
                    if (lane < 16) S->g[t * 16 + lane] = w;
                }
            } else if (wid == 1) {
                float w = (lane < 16) ? S->g[31 * 16 + lane] : 0.f;
                for (int t = 30; t >= 17; --t) {
                    float gv = (lane < 16) ? S->g[t * 16 + lane] : 0.f;
                    const float* Ur = &S->Ub[t * 16 * LS + (lane & 15) * LS];
                    float a0 = 0.f, a1 = 0.f;
                    #pragma unroll
                    for (int k = 0; k < 16; k += 2) {
                        a0 += Ur[k]     * __shfl_sync(0xffffffffu, w, k);
                        a1 += Ur[k + 1] * __shfl_sync(0xffffffffu, w, k + 1);
                    }
                    w = gv + a0 + a1;
                    if (lane < 16) S->g[t * 16 + lane] = w;
                }
            }
            __syncthreads();
            // ---- middle rhs ----
            if (wid == 0 && lane < 16) {
                const float* Uf16 = &S->Uf[16 * 16 * LS + lane * LS];
                const float* Ub16 = &S->Ub[16 * 16 * LS + lane * LS];
                const float* w15  = &S->g[15 * 16];
                const float* w17  = &S->g[17 * 16];
                float acc = S->g[16 * 16 + lane];
                #pragma unroll
                for (int k = 0; k < 16; ++k) acc += Uf16[k] * w15[k] + Ub16[k] * w17[k];
                S->g[16 * 16 + lane] = acc;
            }
            __syncthreads();
            // ---- parallel: Pw_t = inv_t * w_t ----
            for (int idx = tid; idx < NZd; idx += NTHR) {
                int t = idx >> 4, i = idx & 15;
                const float* Pi = &S->inv[t * 16 * LS + i * LS];
                const float* wv = &S->g[t * 16];
                float a0 = 0.f, a1 = 0.f;
                #pragma unroll
                for (int k = 0; k < 16; k += 2) { a0 += Pi[k] * wv[k]; a1 += Pi[k+1] * wv[k+1]; }
                S->Pw[idx] = a0 + a1;
            }
            __syncthreads();
            // ---- outward passes ----
            if (wid == 0) {
                float dz = (lane < 16) ? S->Pw[16 * 16 + lane] : 0.f;
                if (lane < 16) S->g[16 * 16 + lane] = dz;
                for (int t = 15; t >= 0; --t) {
                    float acc = (lane < 16) ? S->Pw[t * 16 + lane] : 0.f;
                    const float* Uc = &S->Uf[(t + 1) * 16 * LS];
                    #pragma unroll
                    for (int k = 0; k < 12; ++k)
                        acc += Uc[k * LS + (lane & 15)] * __shfl_sync(0xffffffffu, dz, k);
                    dz = acc;
                    if (lane < 16) S->g[t * 16 + lane] = dz;
                }
            } else if (wid == 1) {
                float dz = (lane < 16) ? S->Pw[16 * 16 + lane] : 0.f;
                for (int t = 17; t <= 31; ++t) {
                    float acc = (lane < 16) ? S->Pw[t * 16 + lane] : 0.f;
                    const float* Uc = &S->Ub[(t - 1) * 16 * LS];
                    #pragma unroll
                    for (int k = 0; k < 16; ++k)
                        acc += Uc[k * LS + (lane & 15)] * __shfl_sync(0xffffffffu, dz, k);
                    dz = acc;
                    if (lane < 16) S->g[t * 16 + lane] = dz;
                }
            }
            __syncthreads();
            // ---- z -= dz ----
            for (int idx = tid; idx < NZd; idx += NTHR) S->z[idx] -= S->g[idx];
            __syncthreads();
        } // newton

        // ---- multiplier updates ----
        for (int idx = tid; idx < NEQ; idx += NTHR) {
            int t = idx / 12, i = idx % 12;
            float r;
            if (t == 0) r = S->z[i] - S->x0[i];
            else {
                float acc = S->z[t * 16 + i];
                const float* zp = &S->z[(t - 1) * 16];
                const float* Mr = &S->M[i * 16];
                #pragma unroll
                for (int k = 0; k < 16; ++k) acc -= Mr[k] * zp[k];
                r = acc;
            }
            S->lamE[idx] += rho * r;
        }
        for (int idx = tid; idx < NIN; idx += NTHR) {
            int t = idx >> 2, j = idx & 3;
            float uv = S->z[t * 16 + 12 + j];
            S->lamU[idx] = fmaxf(S->lamU[idx] + rho * (uv - S->up[idx]), 0.f);
            S->lamL[idx] = fmaxf(S->lamL[idx] + rho * (S->lo[idx] - uv), 0.f);
        }
        __syncthreads();
        rho = fminf(rho * 10.f, 100.f);
    } // al

    // ---------------- outputs: x [NB,T,NS] then u [NB,T,NC] ----------------
    for (int idx = tid; idx < NEQ; idx += NTHR) {
        int t = idx / 12, i = idx % 12;
        out[b * (Td * NSd) + idx] = S->z[t * 16 + i];
    }
    for (int idx = tid; idx < NIN; idx += NTHR) {
        int t = idx >> 2, j = idx & 3;
        out[NB * (Td * NSd) + b * (Td * NCd) + idx] = S->z[t * 16 + 12 + j];
    }
}

extern "C" void kernel_launch(void* const* d_in, const int* in_sizes, int n_in,
                              void* d_out, int out_size)
{
    const float* x0 = (const float*)d_in[0];
    const float* Q  = (const float*)d_in[1];
    const float* c  = (const float*)d_in[2];
    const float* A  = (const float*)d_in[3];
    const float* B  = (const float*)d_in[4];
    const float* lo = (const float*)d_in[5];
    const float* up = (const float*)d_in[6];
    float* out = (float*)d_out;

    int NB = in_sizes[0] / NSd;   // 64
    size_t smem = sizeof(Smem);
    cudaFuncSetAttribute(mpc_kernel, cudaFuncAttributeMaxDynamicSharedMemorySize, (int)smem);
    mpc_kernel<<<NB, NTHR, smem>>>(x0, Q, c, A, B, lo, up, out, NB);
}

// round 9
// speedup vs baseline: 1.1340x; 1.1340x over previous
#include <cuda_runtime.h>
#include <math.h>

#define NSd   12
#define NCd   4
#define Td    32
#define NZd   512          // T * 16
#define NEQ   384
#define NIN   128
#define DAMPv 1e-4f
#define LS    17           // padded row stride
#define NTHR  128

struct Smem {
    float M[192];             // [A|B] row-major, 12x16
    float MtM[256];
    float x0[12];
    float z[NZd], Qd[NZd], cd[NZd], g[NZd], Pw[NZd];
    float lamE[NEQ], lamU[NIN], lamL[NIN], lo[NIN], up[NIN];
    float Yv[NEQ];
    float Pa[16 * LS], Pb[16 * LS];
    float inv[32 * 16 * LS];  // t<=16: Pinv (fwd);  t>=17: Qbinv (bwd)
    float Uf[17 * 16 * LS];   // Uf[t] = rho*M*Pinv_{t-1}, rows>=12 zero
    float Ub[31 * 16 * LS];   // Ub[t] = rho*M^T*S*Qbinv_{t+1}, full
    int   act[NIN];
    int   fmin, fmax;
};

__device__ __forceinline__ float buildD(const Smem* S, int t, int i, int j, float rho) {
    float v = (t < Td - 1) ? rho * S->MtM[i * 16 + j] : 0.f;
    if (i == j) {
        v += S->Qd[t * 16 + i] + DAMPv;
        if (i < 12) v += rho;
        else {
            int a = S->act[t * 4 + (i - 12)];
            if (a & 1) v += rho;
            if (a & 2) v += rho;
        }
    }
    return v;
}

// split-lane branch-free Gauss-Jordan (single matrix, one warp)
__device__ __forceinline__ void gj16s(const float* Psrc, float* dst, int lane) {
    const int r  = lane & 15;
    const int h  = (lane >> 4) & 1;
    const int c0 = h << 3;
    float a[8];
    #pragma unroll
    for (int j = 0; j < 8; ++j) a[j] = Psrc[r * LS + c0 + j];
    #pragma unroll
    for (int k = 0; k < 16; ++k) {
        const int kh = k >> 3, kc = k & 7;
        float p   = __shfl_sync(0xffffffffu, a[kc], k + (kh << 4));
        float inv = __fdividef(1.0f, p);
        float f   = __shfl_sync(0xffffffffu, a[kc], r + (kh << 4));
        float fi  = f * inv;
        bool  isk = (r == k);
        #pragma unroll
        for (int j = 0; j < 8; ++j) {
            float rkj = __shfl_sync(0xffffffffu, a[j], k + (h << 4));
            a[j] = isk ? rkj * inv : a[j] - fi * rkj;
        }
        if (h == kh) a[kc] = isk ? inv : -fi;
    }
    #pragma unroll
    for (int j = 0; j < 8; ++j) dst[r * LS + c0 + j] = a[j];
}

__global__ __launch_bounds__(NTHR, 1)
void mpc_kernel(const float* __restrict__ x0g, const float* __restrict__ Qg,
                const float* __restrict__ cg,  const float* __restrict__ Ag,
                const float* __restrict__ Bg,  const float* __restrict__ log_,
                const float* __restrict__ upg, float* __restrict__ out, int NB)
{
    extern __shared__ float smraw[];
    Smem* S = reinterpret_cast<Smem*>(smraw);
    const int b    = blockIdx.x;
    const int tid  = threadIdx.x;
    const int wid  = tid >> 5;
    const int lane = tid & 31;

    // ---------------- load inputs ----------------
    for (int i = tid; i < NZd; i += NTHR) {
        S->z[i]  = 0.f;
        S->Qd[i] = Qg[b * NZd + i];
        S->cd[i] = cg[b * NZd + i];
    }
    for (int i = tid; i < NEQ; i += NTHR) S->lamE[i] = 0.f;
    for (int i = tid; i < NIN; i += NTHR) {
        S->lamU[i] = 0.f; S->lamL[i] = 0.f;
        S->lo[i]  = log_[b * NIN + i];
        S->up[i]  = upg[b * NIN + i];
        S->act[i] = -1;
    }
    for (int i = tid; i < 192; i += NTHR) {
        int r = i / 16, cc = i % 16;
        S->M[i] = (cc < 12) ? Ag[r * 12 + cc] : Bg[r * 4 + (cc - 12)];
    }
    if (tid < 12) S->x0[tid] = x0g[b * 12 + tid];
    __syncthreads();

    // ---------------- MtM ----------------
    for (int e = tid; e < 256; e += NTHR) {
        int ri = e >> 4, rj = e & 15;
        float a = 0.f;
        #pragma unroll
        for (int k = 0; k < 12; ++k) a += S->M[k * 16 + ri] * S->M[k * 16 + rj];
        S->MtM[e] = a;
    }

    // ---------------- initial rollout (warp 0) ----------------
    if (tid < 32) {
        if (tid < 12) S->z[tid] = S->x0[tid];
        for (int t = 0; t < Td - 1; ++t) {
            __syncwarp();
            if (tid < 12) {
                float acc = 0.f;
                #pragma unroll
                for (int j = 0; j < 12; ++j) acc += S->M[tid * 16 + j] * S->z[t * 16 + j];
                S->z[(t + 1) * 16 + tid] = acc;
            }
        }
    }
    __syncthreads();

    float rho = 1.f;
    for (int al = 0; al < 3; ++al) {
        for (int nt = 0; nt < 3; ++nt) {
            // ---- Yv = rho*r + lamE ----
            if (tid == 0) { S->fmin = 32; S->fmax = -1; }
            for (int idx = tid; idx < NEQ; idx += NTHR) {
                int t = idx / 12, i = idx % 12;
                float r;
                if (t == 0) r = S->z[i] - S->x0[i];
                else {
                    float acc = S->z[t * 16 + i];
                    const float* zp = &S->z[(t - 1) * 16];
                    const float* Mr = &S->M[i * 16];
                    #pragma unroll
                    for (int k = 0; k < 16; ++k) acc -= Mr[k] * zp[k];
                    r = acc;
                }
                S->Yv[idx] = rho * r + S->lamE[idx];
            }
            __syncthreads();
            // ---- gradient + active-set flip tracking ----
            for (int idx = tid; idx < NZd; idx += NTHR) {
                int t = idx >> 4, i = idx & 15;
                float gv = S->Qd[idx] * S->z[idx] + S->cd[idx];
                if (i < 12) gv += S->Yv[t * 12 + i];
                if (t < Td - 1) {
                    const float* Yn = &S->Yv[(t + 1) * 12];
                    float acc = 0.f;
                    #pragma unroll
                    for (int k = 0; k < 12; ++k) acc += S->M[k * 16 + i] * Yn[k];
                    gv -= acc;
                }
                if (i >= 12) {
                    int u = t * 4 + (i - 12);
                    float su = fmaxf(rho * (S->z[idx] - S->up[u]) + S->lamU[u], 0.f);
                    float sl = fmaxf(rho * (S->lo[u] - S->z[idx]) + S->lamL[u], 0.f);
                    gv += su - sl;
                    int a = (su > 0.f ? 1 : 0) | (sl > 0.f ? 2 : 0);
                    if (a != S->act[u]) {
                        S->act[u] = a;
                        atomicMin(&S->fmin, t);
                        atomicMax(&S->fmax, t);
                    }
                }
                S->g[idx] = gv;
            }
            __syncthreads();
            int fmn = (nt == 0) ? 0  : S->fmin;
            int fmx = (nt == 0) ? 31 : S->fmax;
            bool needFactor = (nt == 0) || (fmx >= 0);

            // Active set unchanged (nt>0): previous Newton step already minimized
            // this quadratic piece -> dz ~ roundoff. Skip the whole solve.
            if (!needFactor) continue;

            {
                int sstart = min(fmn, 31 - fmx);
                if (sstart < 0) sstart = 0;
                if (sstart > 15) sstart = 16;
                for (int s = sstart; s < 16; ++s) {
                    const int tf = s, tb = 31 - s;
                    const bool doF  = (tf >= fmn);
                    const bool doFU = doF && (tf > 0) && (tf - 1 >= fmn);
                    const bool doB  = (s < 15) && (fmx >= tb);
                    const bool doBU = doB && (fmx >= tb + 1);
                    // U builds
                    for (int e = tid; e < 256; e += NTHR) {
                        int ri = e >> 4, rj = e & 15;
                        if (doFU) {
                            float v = 0.f;
                            if (ri < 12) {
                                const float* Pp = &S->inv[(tf - 1) * 16 * LS];
                                const float* Mr = &S->M[ri * 16];
                                float a0 = 0.f, a1 = 0.f;
                                #pragma unroll
                                for (int m = 0; m < 16; m += 2) {
                                    a0 += Mr[m]     * Pp[m * LS + rj];
                                    a1 += Mr[m + 1] * Pp[(m + 1) * LS + rj];
                                }
                                v = rho * (a0 + a1);
                            }
                            S->Uf[tf * 16 * LS + ri * LS + rj] = v;
                        }
                        if (doBU) {
                            const float* Qp = &S->inv[(tb + 1) * 16 * LS];
                            float a0 = 0.f, a1 = 0.f;
                            #pragma unroll
                            for (int m = 0; m < 12; m += 2) {
                                a0 += S->M[m * 16 + ri]       * Qp[m * LS + rj];
                                a1 += S->M[(m + 1) * 16 + ri] * Qp[(m + 1) * LS + rj];
                            }
                            S->Ub[tb * 16 * LS + ri * LS + rj] = rho * (a0 + a1);
                        }
                    }
                    __syncwarp();
                    // P builds
                    for (int e = tid; e < 256; e += NTHR) {
                        int ri = e >> 4, rj = e & 15;
                        if (doF) {
                            float v = buildD(S, tf, ri, rj, rho);
                            if (tf > 0 && ri < 12 && rj < 12) {
                                const float* Ur = &S->Uf[tf * 16 * LS + ri * LS];
                                const float* Mr = &S->M[rj * 16];
                                float a0 = 0.f, a1 = 0.f;
                                #pragma unroll
                                for (int k = 0; k < 16; k += 2) { a0 += Ur[k] * Mr[k]; a1 += Ur[k+1] * Mr[k+1]; }
                                v -= rho * (a0 + a1);
                            }
                            S->Pa[ri * LS + rj] = v;
                        }
                        if (doB) {
                            float v = buildD(S, tb, ri, rj, rho);
                            if (s > 0) {
                                const float* Ur = &S->Ub[tb * 16 * LS + ri * LS];
                                float a0 = 0.f, a1 = 0.f;
                                #pragma unroll
                                for (int k = 0; k < 12; k += 2) {
                                    a0 += Ur[k]     * S->M[k * 16 + rj];
                                    a1 += Ur[k + 1] * S->M[(k + 1) * 16 + rj];
                                }
                                v -= rho * (a0 + a1);
                            }
                            S->Pb[ri * LS + rj] = v;
                        }
                    }
                    __syncthreads();
                    // concurrent inversions: one matrix per warp (separate SMSPs)
                    if (wid == 0 && doF)      gj16s(S->Pa, &S->inv[tf * 16 * LS], lane);
                    else if (wid == 1 && doB) gj16s(S->Pb, &S->inv[tb * 16 * LS], lane);
                    __syncthreads();
                }
                // ---- middle block t=16 ----
                {
                    const bool doMUf = (fmn <= 15);
                    const bool doMUb = (fmx >= 17);
                    for (int e = tid; e < 256; e += NTHR) {
                        int ri = e >> 4, rj = e & 15;
                        if (doMUf) {
                            float v = 0.f;
                            if (ri < 12) {
                                const float* Pp = &S->inv[15 * 16 * LS];
                                const float* Mr = &S->M[ri * 16];
                                float a0 = 0.f, a1 = 0.f;
                                #pragma unroll
                                for (int m = 0; m < 16; m += 2) {
                                    a0 += Mr[m] * Pp[m * LS + rj];
                                    a1 += Mr[m + 1] * Pp[(m + 1) * LS + rj];
                                }
                                v = rho * (a0 + a1);
                            }
                            S->Uf[16 * 16 * LS + ri * LS + rj] = v;
                        }
                        if (doMUb) {
                            const float* Qp = &S->inv[17 * 16 * LS];
                            float a0 = 0.f, a1 = 0.f;
                            #pragma unroll
                            for (int m = 0; m < 12; m += 2) {
                                a0 += S->M[m * 16 + ri] * Qp[m * LS + rj];
                                a1 += S->M[(m + 1) * 16 + ri] * Qp[(m + 1) * LS + rj];
                            }
                            S->Ub[16 * 16 * LS + ri * LS + rj] = rho * (a0 + a1);
                        }
                    }
                    __syncwarp();
                    for (int e = tid; e < 256; e += NTHR) {
                        int ri = e >> 4, rj = e & 15;
                        float pv = buildD(S, 16, ri, rj, rho);
                        if (ri < 12 && rj < 12) {
                            const float* Ur = &S->Uf[16 * 16 * LS + ri * LS];
                            const float* Mr = &S->M[rj * 16];
                            float a0 = 0.f;
                            #pragma unroll
                            for (int k = 0; k < 16; ++k) a0 += Ur[k] * Mr[k];
                            pv -= rho * a0;
                        }
                        {
                            const float* Ur = &S->Ub[16 * 16 * LS + ri * LS];
                            float a0 = 0.f;
                            #pragma unroll
                            for (int k = 0; k < 12; ++k) a0 += Ur[k] * S->M[k * 16 + rj];
                            pv -= rho * a0;
                        }
                        S->Pa[ri * LS + rj] = pv;
                    }
                    __syncthreads();
                    if (wid == 0) gj16s(S->Pa, &S->inv[16 * 16 * LS], lane);
                    __syncthreads();
                }
            }

            // ---- elimination sweeps (warp 0 fwd, warp 1 bwd, concurrent) ----
            if (wid == 0) {
                float w = (lane < 16) ? S->g[lane] : 0.f;
                for (int t = 1; t <= 15; ++t) {
                    float gv = (lane < 16) ? S->g[t * 16 + lane] : 0.f;
                    const float* Ur = &S->Uf[t * 16 * LS + (lane & 15) * LS];
                    float a0 = 0.f, a1 = 0.f;
                    #pragma unroll
                    for (int k = 0; k < 16; k += 2) {
                        a0 += Ur[k]     * __shfl_sync(0xffffffffu, w, k);
                        a1 += Ur[k + 1] * __shfl_sync(0xffffffffu, w, k + 1);
                    }
                    w = gv + a0 + a1;
                    if (lane < 16) S->g[t * 16 + lane] = w;
                }
            } else if (wid == 1) {
                float w = (lane < 16) ? S->g[31 * 16 + lane] : 0.f;
                for (int t = 30; t >= 17; --t) {
                    float gv = (lane < 16) ? S->g[t * 16 + lane] : 0.f;
                    const float* Ur = &S->Ub[t * 16 * LS + (lane & 15) * LS];
                    float a0 = 0.f, a1 = 0.f;
                    #pragma unroll
                    for (int k = 0; k < 16; k += 2) {
                        a0 += Ur[k]     * __shfl_sync(0xffffffffu, w, k);
                        a1 += Ur[k + 1] * __shfl_sync(0xffffffffu, w, k + 1);
                    }
                    w = gv + a0 + a1;
                    if (lane < 16) S->g[t * 16 + lane] = w;
                }
            }
            __syncthreads();
            // ---- middle rhs ----
            if (wid == 0 && lane < 16) {
                const float* Uf16 = &S->Uf[16 * 16 * LS + lane * LS];
                const float* Ub16 = &S->Ub[16 * 16 * LS + lane * LS];
                const float* w15  = &S->g[15 * 16];
                const float* w17  = &S->g[17 * 16];
                float acc = S->g[16 * 16 + lane];
                #pragma unroll
                for (int k = 0; k < 16; ++k) acc += Uf16[k] * w15[k] + Ub16[k] * w17[k];
                S->g[16 * 16 + lane] = acc;
            }
            __syncthreads();
            // ---- parallel: Pw_t = inv_t * w_t ----
            for (int idx = tid; idx < NZd; idx += NTHR) {
                int t = idx >> 4, i = idx & 15;
                const float* Pi = &S->inv[t * 16 * LS + i * LS];
                const float* wv = &S->g[t * 16];
                float a0 = 0.f, a1 = 0.f;
                #pragma unroll
                for (int k = 0; k < 16; k += 2) { a0 += Pi[k] * wv[k]; a1 += Pi[k+1] * wv[k+1]; }
                S->Pw[idx] = a0 + a1;
            }
            __syncthreads();
            // ---- outward passes ----
            if (wid == 0) {
                float dz = (lane < 16) ? S->Pw[16 * 16 + lane] : 0.f;
                if (lane < 16) S->g[16 * 16 + lane] = dz;
                for (int t = 15; t >= 0; --t) {
                    float acc = (lane < 16) ? S->Pw[t * 16 + lane] : 0.f;
                    const float* Uc = &S->Uf[(t + 1) * 16 * LS];
                    #pragma unroll
                    for (int k = 0; k < 12; ++k)
                        acc += Uc[k * LS + (lane & 15)] * __shfl_sync(0xffffffffu, dz, k);
                    dz = acc;
                    if (lane < 16) S->g[t * 16 + lane] = dz;
                }
            } else if (wid == 1) {
                float dz = (lane < 16) ? S->Pw[16 * 16 + lane] : 0.f;
                for (int t = 17; t <= 31; ++t) {
                    float acc = (lane < 16) ? S->Pw[t * 16 + lane] : 0.f;
                    const float* Uc = &S->Ub[(t - 1) * 16 * LS];
                    #pragma unroll
                    for (int k = 0; k < 16; ++k)
                        acc += Uc[k * LS + (lane & 15)] * __shfl_sync(0xffffffffu, dz, k);
                    dz = acc;
                    if (lane < 16) S->g[t * 16 + lane] = dz;
                }
            }
            __syncthreads();
            // ---- z -= dz ----
            for (int idx = tid; idx < NZd; idx += NTHR) S->z[idx] -= S->g[idx];
            __syncthreads();
        } // newton

        // ---- multiplier updates ----
        for (int idx = tid; idx < NEQ; idx += NTHR) {
            int t = idx / 12, i = idx % 12;
            float r;
            if (t == 0) r = S->z[i] - S->x0[i];
            else {
                float acc = S->z[t * 16 + i];
                const float* zp = &S->z[(t - 1) * 16];
                const float* Mr = &S->M[i * 16];
                #pragma unroll
                for (int k = 0; k < 16; ++k) acc -= Mr[k] * zp[k];
                r = acc;
            }
            S->lamE[idx] += rho * r;
        }
        for (int idx = tid; idx < NIN; idx += NTHR) {
            int t = idx >> 2, j = idx & 3;
            float uv = S->z[t * 16 + 12 + j];
            S->lamU[idx] = fmaxf(S->lamU[idx] + rho * (uv - S->up[idx]), 0.f);
            S->lamL[idx] = fmaxf(S->lamL[idx] + rho * (S->lo[idx] - uv), 0.f);
        }
        __syncthreads();
        rho = fminf(rho * 10.f, 100.f);
    } // al

    // ---------------- outputs: x [NB,T,NS] then u [NB,T,NC] ----------------
    for (int idx = tid; idx < NEQ; idx += NTHR) {
        int t = idx / 12, i = idx % 12;
        out[b * (Td * NSd) + idx] = S->z[t * 16 + i];
    }
    for (int idx = tid; idx < NIN; idx += NTHR) {
        int t = idx >> 2, j = idx & 3;
        out[NB * (Td * NSd) + b * (Td * NCd) + idx] = S->z[t * 16 + 12 + j];
    }
}

extern "C" void kernel_launch(void* const* d_in, const int* in_sizes, int n_in,
                              void* d_out, int out_size)
{
    const float* x0 = (const float*)d_in[0];
    const float* Q  = (const float*)d_in[1];
    const float* c  = (const float*)d_in[2];
    const float* A  = (const float*)d_in[3];
    const float* B  = (const float*)d_in[4];
    const float* lo = (const float*)d_in[5];
    const float* up = (const float*)d_in[6];
    float* out = (float*)d_out;

    int NB = in_sizes[0] / NSd;   // 64
    size_t smem = sizeof(Smem);
    cudaFuncSetAttribute(mpc_kernel, cudaFuncAttributeMaxDynamicSharedMemorySize, (int)smem);
    mpc_kernel<<<NB, NTHR, smem>>>(x0, Q, c, A, B, lo, up, out, NB);
}

// round 10
// speedup vs baseline: 1.1476x; 1.0120x over previous
#include <cuda_runtime.h>
#include <math.h>

#define NSd   12
#define NCd   4
#define Td    32
#define NZd   512          // T * 16
#define NEQ   384
#define NIN   128
#define DAMPv 1e-4f
#define LS    17           // padded row stride
#define NTHR  128

struct Smem {
    float M[192];             // [A|B] row-major, 12x16
    float MtM[256];
    float x0[12];
    float z[NZd], Qd[NZd], cd[NZd], g[NZd], Pw[NZd];
    float lamE[NEQ], lamU[NIN], lamL[NIN], lo[NIN], up[NIN];
    float Yv[NEQ];
    float Pa[16 * LS], Pb[16 * LS];
    float inv[32 * 16 * LS];  // t<=16: Pinv (fwd);  t>=17: Qbinv (bwd)
    float Uf[17 * 16 * LS];   // Uf[t] = rho*M*Pinv_{t-1}, rows>=12 zero
    float Ub[31 * 16 * LS];   // Ub[t] = rho*M^T*S*Qbinv_{t+1}, full
    int   act[NIN];
    int   fmin, fmax;
};

__device__ __forceinline__ float buildD(const Smem* S, int t, int i, int j, float rho) {
    float v = (t < Td - 1) ? rho * S->MtM[i * 16 + j] : 0.f;
    if (i == j) {
        v += S->Qd[t * 16 + i] + DAMPv;
        if (i < 12) v += rho;
        else {
            int a = S->act[t * 4 + (i - 12)];
            if (a & 1) v += rho;
            if (a & 2) v += rho;
        }
    }
    return v;
}

// split-lane branch-free Gauss-Jordan with 2x2 BLOCK pivots (8 serial steps).
// lane = (row r, col-half h); each lane owns 8 columns of its row.
__device__ __forceinline__ void gj16b(const float* Psrc, float* dst, int lane) {
    const int r  = lane & 15;
    const int h  = (lane >> 4) & 1;
    const int c0 = h << 3;
    float a[8];
    #pragma unroll
    for (int j = 0; j < 8; ++j) a[j] = Psrc[r * LS + c0 + j];
    #pragma unroll
    for (int kb = 0; kb < 8; ++kb) {
        const int p  = 2 * kb, q = p + 1;
        const int kh = p >> 3;            // both p,q in same half (p even)
        const int pc = p & 7, qc = q & 7;
        // 2x2 pivot block (old values)
        float bpp = __shfl_sync(0xffffffffu, a[pc], p + (kh << 4));
        float bpq = __shfl_sync(0xffffffffu, a[qc], p + (kh << 4));
        float bqp = __shfl_sync(0xffffffffu, a[pc], q + (kh << 4));
        float bqq = __shfl_sync(0xffffffffu, a[qc], q + (kh << 4));
        float idet = __fdividef(1.0f, bpp * bqq - bpq * bqp);
        float i00 =  bqq * idet, i01 = -bpq * idet;
        float i10 = -bqp * idet, i11 =  bpp * idet;
        // this lane's row factor F = (a[r][p], a[r][q]); G = F * Binv
        float f0 = __shfl_sync(0xffffffffu, a[pc], r + (kh << 4));
        float f1 = __shfl_sync(0xffffffffu, a[qc], r + (kh << 4));
        float g0 = f0 * i00 + f1 * i10;
        float g1 = f0 * i01 + f1 * i11;
        const bool isp = (r == p), isq = (r == q);
        #pragma unroll
        for (int j = 0; j < 8; ++j) {
            float R0 = __shfl_sync(0xffffffffu, a[j], p + (h << 4));  // old pivot rows
            float R1 = __shfl_sync(0xffffffffu, a[j], q + (h << 4));
            float np  = i00 * R0 + i01 * R1;     // new row p
            float nq  = i10 * R0 + i11 * R1;     // new row q
            float upd = a[j] - g0 * R0 - g1 * R1;
            a[j] = isp ? np : (isq ? nq : upd);
        }
        // pivot-block column fixup (G*B == F makes in-loop values 0/identity; overwrite)
        if (h == kh) {
            a[pc] = isp ? i00 : (isq ? i10 : -g0);
            a[qc] = isp ? i01 : (isq ? i11 : -g1);
        }
    }
    #pragma unroll
    for (int j = 0; j < 8; ++j) dst[r * LS + c0 + j] = a[j];
}

__global__ __launch_bounds__(NTHR, 1)
void mpc_kernel(const float* __restrict__ x0g, const float* __restrict__ Qg,
                const float* __restrict__ cg,  const float* __restrict__ Ag,
                const float* __restrict__ Bg,  const float* __restrict__ log_,
                const float* __restrict__ upg, float* __restrict__ out, int NB)
{
    extern __shared__ float smraw[];
    Smem* S = reinterpret_cast<Smem*>(smraw);
    const int b    = blockIdx.x;
    const int tid  = threadIdx.x;
    const int wid  = tid >> 5;
    const int lane = tid & 31;

    // ---------------- load inputs ----------------
    for (int i = tid; i < NZd; i += NTHR) {
        S->z[i]  = 0.f;
        S->Qd[i] = Qg[b * NZd + i];
        S->cd[i] = cg[b * NZd + i];
    }
    for (int i = tid; i < NEQ; i += NTHR) S->lamE[i] = 0.f;
    for (int i = tid; i < NIN; i += NTHR) {
        S->lamU[i] = 0.f; S->lamL[i] = 0.f;
        S->lo[i]  = log_[b * NIN + i];
        S->up[i]  = upg[b * NIN + i];
        S->act[i] = -1;
    }
    for (int i = tid; i < 192; i += NTHR) {
        int r = i / 16, cc = i % 16;
        S->M[i] = (cc < 12) ? Ag[r * 12 + cc] : Bg[r * 4 + (cc - 12)];
    }
    if (tid < 12) S->x0[tid] = x0g[b * 12 + tid];
    __syncthreads();

    // ---------------- MtM ----------------
    for (int e = tid; e < 256; e += NTHR) {
        int ri = e >> 4, rj = e & 15;
        float a = 0.f;
        #pragma unroll
        for (int k = 0; k < 12; ++k) a += S->M[k * 16 + ri] * S->M[k * 16 + rj];
        S->MtM[e] = a;
    }

    // ---------------- initial rollout (warp 0) ----------------
    if (tid < 32) {
        if (tid < 12) S->z[tid] = S->x0[tid];
        for (int t = 0; t < Td - 1; ++t) {
            __syncwarp();
            if (tid < 12) {
                float acc = 0.f;
                #pragma unroll
                for (int j = 0; j < 12; ++j) acc += S->M[tid * 16 + j] * S->z[t * 16 + j];
                S->z[(t + 1) * 16 + tid] = acc;
            }
        }
    }
    __syncthreads();

    float rho = 1.f;
    for (int al = 0; al < 3; ++al) {
        for (int nt = 0; nt < 3; ++nt) {
            // ---- Yv = rho*r + lamE ----
            if (tid == 0) { S->fmin = 32; S->fmax = -1; }
            for (int idx = tid; idx < NEQ; idx += NTHR) {
                int t = idx / 12, i = idx % 12;
                float r;
                if (t == 0) r = S->z[i] - S->x0[i];
                else {
                    float acc = S->z[t * 16 + i];
                    const float* zp = &S->z[(t - 1) * 16];
                    const float* Mr = &S->M[i * 16];
                    #pragma unroll
                    for (int k = 0; k < 16; ++k) acc -= Mr[k] * zp[k];
                    r = acc;
                }
                S->Yv[idx] = rho * r + S->lamE[idx];
            }
            __syncthreads();
            // ---- gradient + active-set flip tracking ----
            for (int idx = tid; idx < NZd; idx += NTHR) {
                int t = idx >> 4, i = idx & 15;
                float gv = S->Qd[idx] * S->z[idx] + S->cd[idx];
                if (i < 12) gv += S->Yv[t * 12 + i];
                if (t < Td - 1) {
                    const float* Yn = &S->Yv[(t + 1) * 12];
                    float acc = 0.f;
                    #pragma unroll
                    for (int k = 0; k < 12; ++k) acc += S->M[k * 16 + i] * Yn[k];
                    gv -= acc;
                }
                if (i >= 12) {
                    int u = t * 4 + (i - 12);
                    float su = fmaxf(rho * (S->z[idx] - S->up[u]) + S->lamU[u], 0.f);
                    float sl = fmaxf(rho * (S->lo[u] - S->z[idx]) + S->lamL[u], 0.f);
                    gv += su - sl;
                    int a = (su > 0.f ? 1 : 0) | (sl > 0.f ? 2 : 0);
                    if (a != S->act[u]) {
                        S->act[u] = a;
                        atomicMin(&S->fmin, t);
                        atomicMax(&S->fmax, t);
                    }
                }
                S->g[idx] = gv;
            }
            __syncthreads();
            int fmn = (nt == 0) ? 0  : S->fmin;
            int fmx = (nt == 0) ? 31 : S->fmax;
            bool needFactor = (nt == 0) || (fmx >= 0);

            // Active set unchanged (nt>0): previous Newton step already minimized
            // this quadratic piece -> dz ~ roundoff. Skip the whole solve.
            if (!needFactor) continue;

            {
                int sstart = min(fmn, 31 - fmx);
                if (sstart < 0) sstart = 0;
                if (sstart > 15) sstart = 16;
                for (int s = sstart; s < 16; ++s) {
                    const int tf = s, tb = 31 - s;
                    const bool doF  = (tf >= fmn);
                    const bool doFU = doF && (tf > 0) && (tf - 1 >= fmn);
                    const bool doB  = (s < 15) && (fmx >= tb);
                    const bool doBU = doB && (fmx >= tb + 1);
                    // U builds
                    for (int e = tid; e < 256; e += NTHR) {
                        int ri = e >> 4, rj = e & 15;
                        if (doFU) {
                            float v = 0.f;
                            if (ri < 12) {
                                const float* Pp = &S->inv[(tf - 1) * 16 * LS];
                                const float* Mr = &S->M[ri * 16];
                                float a0 = 0.f, a1 = 0.f;
                                #pragma unroll
                                for (int m = 0; m < 16; m += 2) {
                                    a0 += Mr[m]     * Pp[m * LS + rj];
                                    a1 += Mr[m + 1] * Pp[(m + 1) * LS + rj];
                                }
                                v = rho * (a0 + a1);
                            }
                            S->Uf[tf * 16 * LS + ri * LS + rj] = v;
                        }
                        if (doBU) {
                            const float* Qp = &S->inv[(tb + 1) * 16 * LS];
                            float a0 = 0.f, a1 = 0.f;
                            #pragma unroll
                            for (int m = 0; m < 12; m += 2) {
                                a0 += S->M[m * 16 + ri]       * Qp[m * LS + rj];
                                a1 += S->M[(m + 1) * 16 + ri] * Qp[(m + 1) * LS + rj];
                            }
                            S->Ub[tb * 16 * LS + ri * LS + rj] = rho * (a0 + a1);
                        }
                    }
                    __syncwarp();
                    // P builds
                    for (int e = tid; e < 256; e += NTHR) {
                        int ri = e >> 4, rj = e & 15;
                        if (doF) {
                            float v = buildD(S, tf, ri, rj, rho);
                            if (tf > 0 && ri < 12 && rj < 12) {
                                const float* Ur = &S->Uf[tf * 16 * LS + ri * LS];
                                const float* Mr = &S->M[rj * 16];
                                float a0 = 0.f, a1 = 0.f;
                                #pragma unroll
                                for (int k = 0; k < 16; k += 2) { a0 += Ur[k] * Mr[k]; a1 += Ur[k+1] * Mr[k+1]; }
                                v -= rho * (a0 + a1);
                            }
                            S->Pa[ri * LS + rj] = v;
                        }
                        if (doB) {
                            float v = buildD(S, tb, ri, rj, rho);
                            if (s > 0) {
                                const float* Ur = &S->Ub[tb * 16 * LS + ri * LS];
                                float a0 = 0.f, a1 = 0.f;
                                #pragma unroll
                                for (int k = 0; k < 12; k += 2) {
                                    a0 += Ur[k]     * S->M[k * 16 + rj];
                                    a1 += Ur[k + 1] * S->M[(k + 1) * 16 + rj];
                                }
                                v -= rho * (a0 + a1);
                            }
                            S->Pb[ri * LS + rj] = v;
                        }
                    }
                    __syncthreads();
                    // concurrent inversions: one matrix per warp (separate SMSPs)
                    if (wid == 0 && doF)      gj16b(S->Pa, &S->inv[tf * 16 * LS], lane);
                    else if (wid == 1 && doB) gj16b(S->Pb, &S->inv[tb * 16 * LS], lane);
                    __syncthreads();
                }
                // ---- middle block t=16 ----
                {
                    const bool doMUf = (fmn <= 15);
                    const bool doMUb = (fmx >= 17);
                    for (int e = tid; e < 256; e += NTHR) {
                        int ri = e >> 4, rj = e & 15;
                        if (doMUf) {
                            float v = 0.f;
                            if (ri < 12) {
                                const float* Pp = &S->inv[15 * 16 * LS];
                                const float* Mr = &S->M[ri * 16];
                                float a0 = 0.f, a1 = 0.f;
                                #pragma unroll
                                for (int m = 0; m < 16; m += 2) {
                                    a0 += Mr[m] * Pp[m * LS + rj];
                                    a1 += Mr[m + 1] * Pp[(m + 1) * LS + rj];
                                }
                                v = rho * (a0 + a1);
                            }
                            S->Uf[16 * 16 * LS + ri * LS + rj] = v;
                        }
                        if (doMUb) {
                            const float* Qp = &S->inv[17 * 16 * LS];
                            float a0 = 0.f, a1 = 0.f;
                            #pragma unroll
                            for (int m = 0; m < 12; m += 2) {
                                a0 += S->M[m * 16 + ri] * Qp[m * LS + rj];
                                a1 += S->M[(m + 1) * 16 + ri] * Qp[(m + 1) * LS + rj];
                            }
                            S->Ub[16 * 16 * LS + ri * LS + rj] = rho * (a0 + a1);
                        }
                    }
                    __syncwarp();
                    for (int e = tid; e < 256; e += NTHR) {
                        int ri = e >> 4, rj = e & 15;
                        float pv = buildD(S, 16, ri, rj, rho);
                        if (ri < 12 && rj < 12) {
                            const float* Ur = &S->Uf[16 * 16 * LS + ri * LS];
                            const float* Mr = &S->M[rj * 16];
                            float a0 = 0.f;
                            #pragma unroll
                            for (int k = 0; k < 16; ++k) a0 += Ur[k] * Mr[k];
                            pv -= rho * a0;
                        }
                        {
                            const float* Ur = &S->Ub[16 * 16 * LS + ri * LS];
                            float a0 = 0.f;
                            #pragma unroll
                            for (int k = 0; k < 12; ++k) a0 += Ur[k] * S->M[k * 16 + rj];
                            pv -= rho * a0;
                        }
                        S->Pa[ri * LS + rj] = pv;
                    }
                    __syncthreads();
                    if (wid == 0) gj16b(S->Pa, &S->inv[16 * 16 * LS], lane);
                    __syncthreads();
                }
            }

            // ---- elimination sweeps (warp 0 fwd, warp 1 bwd, concurrent) ----
            if (wid == 0) {
                float w = (lane < 16) ? S->g[lane] : 0.f;
                for (int t = 1; t <= 15; ++t) {
                    float gv = (lane < 16) ? S->g[t * 16 + lane] : 0.f;
                    const float* Ur = &S->Uf[t * 16 * LS + (lane & 15) * LS];
                    float a0 = 0.f, a1 = 0.f;
                    #pragma unroll
                    for (int k = 0; k < 16; k += 2) {
                        a0 += Ur[k]     * __shfl_sync(0xffffffffu, w, k);
                        a1 += Ur[k + 1] * __shfl_sync(0xffffffffu, w, k + 1);
                    }
                    w = gv + a0 + a1;
                    if (lane < 16) S->g[t * 16 + lane] = w;
                }
            } else if (wid == 1) {
                float w = (lane < 16) ? S->g[31 * 16 + lane] : 0.f;
                for (int t = 30; t >= 17; --t) {
                    float gv = (lane < 16) ? S->g[t * 16 + lane] : 0.f;
                    const float* Ur = &S->Ub[t * 16 * LS + (lane & 15) * LS];
                    float a0 = 0.f, a1 = 0.f;
                    #pragma unroll
                    for (int k = 0; k < 16; k += 2) {
                        a0 += Ur[k]     * __shfl_sync(0xffffffffu, w, k);
                        a1 += Ur[k + 1] * __shfl_sync(0xffffffffu, w, k + 1);
                    }
                    w = gv + a0 + a1;
                    if (lane < 16) S->g[t * 16 + lane] = w;
                }
            }
            __syncthreads();
            // ---- middle rhs ----
            if (wid == 0 && lane < 16) {
                const float* Uf16 = &S->Uf[16 * 16 * LS + lane * LS];
                const float* Ub16 = &S->Ub[16 * 16 * LS + lane * LS];
                const float* w15  = &S->g[15 * 16];
                const float* w17  = &S->g[17 * 16];
                float acc = S->g[16 * 16 + lane];
                #pragma unroll
                for (int k = 0; k < 16; ++k) acc += Uf16[k] * w15[k] + Ub16[k] * w17[k];
                S->g[16 * 16 + lane] = acc;
            }
            __syncthreads();
            // ---- parallel: Pw_t = inv_t * w_t ----
            for (int idx = tid; idx < NZd; idx += NTHR) {
                int t = idx >> 4, i = idx & 15;
                const float* Pi = &S->inv[t * 16 * LS + i * LS];
                const float* wv = &S->g[t * 16];
                float a0 = 0.f, a1 = 0.f;
                #pragma unroll
                for (int k = 0; k < 16; k += 2) { a0 += Pi[k] * wv[k]; a1 += Pi[k+1] * wv[k+1]; }
                S->Pw[idx] = a0 + a1;
            }
            __syncthreads();
            // ---- outward passes ----
            if (wid == 0) {
                float dz = (lane < 16) ? S->Pw[16 * 16 + lane] : 0.f;
                if (lane < 16) S->g[16 * 16 + lane] = dz;
                for (int t = 15; t >= 0; --t) {
                    float acc = (lane < 16) ? S->Pw[t * 16 + lane] : 0.f;
                    const float* Uc = &S->Uf[(t + 1) * 16 * LS];
                    #pragma unroll
                    for (int k = 0; k < 12; ++k)
                        acc += Uc[k * LS + (lane & 15)] * __shfl_sync(0xffffffffu, dz, k);
                    dz = acc;
                    if (lane < 16) S->g[t * 16 + lane] = dz;
                }
            } else if (wid == 1) {
                float dz = (lane < 16) ? S->Pw[16 * 16 + lane] : 0.f;
                for (int t = 17; t <= 31; ++t) {
                    float acc = (lane < 16) ? S->Pw[t * 16 + lane] : 0.f;
                    const float* Uc = &S->Ub[(t - 1) * 16 * LS];
                    #pragma unroll
                    for (int k = 0; k < 16; ++k)
                        acc += Uc[k * LS + (lane & 15)] * __shfl_sync(0xffffffffu, dz, k);
                    dz = acc;
                    if (lane < 16) S->g[t * 16 + lane] = dz;
                }
            }
            __syncthreads();
            // ---- z -= dz ----
            for (int idx = tid; idx < NZd; idx += NTHR) S->z[idx] -= S->g[idx];
            __syncthreads();
        } // newton

        // ---- multiplier updates ----
        for (int idx = tid; idx < NEQ; idx += NTHR) {
            int t = idx / 12, i = idx % 12;
            float r;
            if (t == 0) r = S->z[i] - S->x0[i];
            else {
                float acc = S->z[t * 16 + i];
                const float* zp = &S->z[(t - 1) * 16];
                const float* Mr = &S->M[i * 16];
                #pragma unroll
                for (int k = 0; k < 16; ++k) acc -= Mr[k] * zp[k];
                r = acc;
            }
            S->lamE[idx] += rho * r;
        }
        for (int idx = tid; idx < NIN; idx += NTHR) {
            int t = idx >> 2, j = idx & 3;
            float uv = S->z[t * 16 + 12 + j];
            S->lamU[idx] = fmaxf(S->lamU[idx] + rho * (uv - S->up[idx]), 0.f);
            S->lamL[idx] = fmaxf(S->lamL[idx] + rho * (S->lo[idx] - uv), 0.f);
        }
        __syncthreads();
        rho = fminf(rho * 10.f, 100.f);
    } // al

    // ---------------- outputs: x [NB,T,NS] then u [NB,T,NC] ----------------
    for (int idx = tid; idx < NEQ; idx += NTHR) {
        int t = idx / 12, i = idx % 12;
        out[b * (Td * NSd) + idx] = S->z[t * 16 + i];
    }
    for (int idx = tid; idx < NIN; idx += NTHR) {
        int t = idx >> 2, j = idx & 3;
        out[NB * (Td * NSd) + b * (Td * NCd) + idx] = S->z[t * 16 + 12 + j];
    }
}

extern "C" void kernel_launch(void* const* d_in, const int* in_sizes, int n_in,
                              void* d_out, int out_size)
{
    const float* x0 = (const float*)d_in[0];
    const float* Q  = (const float*)d_in[1];
    const float* c  = (const float*)d_in[2];
    const float* A  = (const float*)d_in[3];
    const float* B  = (const float*)d_in[4];
    const float* lo = (const float*)d_in[5];
    const float* up = (const float*)d_in[6];
    float* out = (float*)d_out;

    int NB = in_sizes[0] / NSd;   // 64
    size_t smem = sizeof(Smem);
    cudaFuncSetAttribute(mpc_kernel, cudaFuncAttributeMaxDynamicSharedMemorySize, (int)smem);
    mpc_kernel<<<NB, NTHR, smem>>>(x0, Q, c, A, B, lo, up, out, NB);
}